// round 11
// baseline (speedup 1.0000x reference)
#include <cuda_runtime.h>

// Persistent single-kernel greedy transducer decode. B=32,T=1000,H=640,V=5000.
// Round 10: B=16 x C=2(adjacent, LDG.64) tiles -> halved L2 weight streaming.
// DEP=40/HS=16, fused B->C2, 2 barriers/step (round-8 skeleton).

typedef unsigned long long ull;

constexpr int kB = 32;
constexpr int kT = 1000;
constexpr int kH = 640;
constexpr int kV = 5000;
constexpr int kG = 2560;

constexpr int NBLK = 592;   // 4 blocks/SM
constexpr int NTHR = 256;

constexpr int HS = 16, DEP = 40;
constexpr int TILES_A = 320;    // 10 vch(512) x 16 hs x 2 bg(16b)
constexpr int TILES_CH = 160;   // 5 jch(512) x 16 hs x 2 bg
constexpr int BCH = 8;          // 8 v-chunks x 32 b = 256 B-units
constexpr int PT = 1565;        // precompute: 313 rowblocks(16v) x 5 jch

// ---- device globals ----
__device__ __align__(16) float d_xwx[(size_t)kV * kH * 4];
__device__ __align__(16) float d_part[(size_t)HS * kB * kV];       // 10.2MB
__device__ __align__(16) float d_gpart[(size_t)HS * kB * kH * 4];  // 5.2MB
__device__ __align__(16) float d_jointT[kH * kB];
__device__ __align__(16) float d_hT[kH * kB];
__device__ __align__(16) float d_c[kB * kH];
__device__ float d_scores[kB];
__device__ int   d_tok[kB];
__device__ float d_bmax[kB * BCH];
__device__ int   d_bidx[kB * BCH];
__device__ float d_bsum[kB * BCH];
__device__ int   d_bcnt[2][kB];

__device__ __align__(128) unsigned g_count[32];
__device__ __align__(128) unsigned g_gen[32];

__device__ __forceinline__ unsigned ld_cg(const unsigned* p) {
    unsigned v;
    asm volatile("ld.global.cg.u32 %0, [%1];" : "=r"(v) : "l"(p));
    return v;
}
__device__ __forceinline__ int ld_cg_i(const int* p) {
    int v;
    asm volatile("ld.global.cg.s32 %0, [%1];" : "=r"(v) : "l"(p));
    return v;
}

__device__ __forceinline__ void grid_barrier() {
    __syncthreads();
    if (threadIdx.x == 0) {
        __threadfence();
        unsigned my = ld_cg(&g_gen[0]);
        if (atomicAdd(&g_count[0], 1u) == (unsigned)(NBLK - 1)) {
            atomicExch(&g_count[0], 0u);
            __threadfence();
            atomicAdd(&g_gen[0], 1u);
        } else {
            while (ld_cg(&g_gen[0]) == my) { __nanosleep(40); }
        }
        __threadfence();
    }
    __syncthreads();
}

// ---- f32x2 helpers ----
__device__ __forceinline__ ull pack2(float w) {
    ull r; asm("mov.b64 %0, {%1, %1};" : "=l"(r) : "f"(w)); return r;
}
__device__ __forceinline__ void ffma2(ull& a, ull s, ull w) {
    asm("fma.rn.f32x2 %0, %1, %2, %0;" : "+l"(a) : "l"(s), "l"(w));
}
__device__ __forceinline__ float2 unpack2(ull a) {
    float2 f; asm("mov.b64 {%0, %1}, %2;" : "=f"(f.x), "=f"(f.y) : "l"(a)); return f;
}
__device__ __forceinline__ float sigf(float x) { return 1.f / (1.f + expf(-x)); }

// B=16 x C=2(adjacent) dot over 40 depth rows. One float2 weight load per row,
// 4-deep ring, 16 FFMA2 per row. wp must be float2-aligned (even column).
__device__ __forceinline__ void dot40p(ull a1[8], ull a2[8], const float (*sA)[16],
                                       const float* __restrict__ wp, size_t ws) {
    const float2* p = reinterpret_cast<const float2*>(wp);
    size_t ws2 = ws >> 1;
    float2 wb[4];
#pragma unroll
    for (int j = 0; j < 4; j++) wb[j] = p[j * ws2];
    const float2* fp = p + 4 * ws2;
#pragma unroll
    for (int g = 0; g < DEP; ++g) {
        float2 w = wb[g & 3];
        if (g < DEP - 4) { wb[g & 3] = *fp; fp += ws2; }
        ull W1 = pack2(w.x), W2 = pack2(w.y);
        const double2* sp = reinterpret_cast<const double2*>(sA[g]);
        double2 q0 = sp[0], q1 = sp[1], q2 = sp[2], q3 = sp[3];
        ull s0 = __double_as_longlong(q0.x), s1 = __double_as_longlong(q0.y);
        ull s2 = __double_as_longlong(q1.x), s3 = __double_as_longlong(q1.y);
        ull s4 = __double_as_longlong(q2.x), s5 = __double_as_longlong(q2.y);
        ull s6 = __double_as_longlong(q3.x), s7 = __double_as_longlong(q3.y);
        ffma2(a1[0], s0, W1); ffma2(a1[1], s1, W1);
        ffma2(a1[2], s2, W1); ffma2(a1[3], s3, W1);
        ffma2(a1[4], s4, W1); ffma2(a1[5], s5, W1);
        ffma2(a1[6], s6, W1); ffma2(a1[7], s7, W1);
        ffma2(a2[0], s0, W2); ffma2(a2[1], s1, W2);
        ffma2(a2[2], s2, W2); ffma2(a2[3], s3, W2);
        ffma2(a2[4], s4, W2); ffma2(a2[5], s5, W2);
        ffma2(a2[6], s6, W2); ffma2(a2[7], s7, W2);
    }
}

// Fill [40][16] tile from transposed [k][32] source (coalesced 64B rows).
__device__ __forceinline__ void fill_T16(float (*dst)[16], const float* __restrict__ srcT,
                                         int bg, int hbase) {
    for (int idx = threadIdx.x; idx < DEP * 16; idx += NTHR) {
        int hh = idx >> 4, bb = idx & 15;
        dst[hh][bb] = srcT[(hbase + hh) * kB + bg * 16 + bb];
    }
}

// ---- A tile: jointT @ Wc -> d_part ----
__device__ void A_tile(int tt, float (*sA)[16], const float* __restrict__ Wc) {
    int hs = tt & 15, vch = (tt >> 4) % 10, bg = tt / 160;
    int hbase = hs * DEP;
    fill_T16(sA, d_jointT, bg, hbase);
    __syncthreads();
    int v = vch * 512 + 2 * threadIdx.x;
    if (v + 1 < kV) {                 // vch=9, tid>=196 -> fully out of range
        ull a1[8] = {0, 0, 0, 0, 0, 0, 0, 0}, a2[8] = {0, 0, 0, 0, 0, 0, 0, 0};
        dot40p(a1, a2, sA, Wc + (size_t)hbase * kV + v, kV);
        size_t rb = (size_t)(hs * kB + bg * 16) * kV + v;
#pragma unroll
        for (int i = 0; i < 8; i++) {
            float2 f1 = unpack2(a1[i]);     // col v,  batches 2i / 2i+1
            float2 f2 = unpack2(a2[i]);     // col v+1
            float2 r0 = make_float2(f1.x, f2.x);
            float2 r1 = make_float2(f1.y, f2.y);
            *reinterpret_cast<float2*>(&d_part[rb + (size_t)(2 * i) * kV]) = r0;
            *reinterpret_cast<float2*>(&d_part[rb + (size_t)(2 * i + 1) * kV]) = r1;
        }
    }
}

// ---- CH tile: hT @ Wh -> d_gpart ----
__device__ void CH_tile(int u, float (*sA)[16], const float* __restrict__ Wh) {
    int hs = u & 15, jch = (u >> 4) % 5, bg = u / 80;
    int hbase = hs * DEP;
    fill_T16(sA, d_hT, bg, hbase);
    __syncthreads();
    int j1 = jch * 512 + 2 * threadIdx.x;
    int j2 = j1 + 1;
    ull a1[8] = {0, 0, 0, 0, 0, 0, 0, 0}, a2[8] = {0, 0, 0, 0, 0, 0, 0, 0};
    dot40p(a1, a2, sA, Wh + (size_t)hbase * kG + j1, kG);
    int g1 = j1 / kH, k1 = j1 - g1 * kH;
    int g2 = j2 / kH, k2 = j2 - g2 * kH;
#pragma unroll
    for (int i = 0; i < 8; i++) {
        float2 f1 = unpack2(a1[i]);
        float2 f2 = unpack2(a2[i]);
        int b0 = bg * 16 + 2 * i;
        d_gpart[(((size_t)hs * kB + b0) * kH + k1) * 4 + g1] = f1.x;
        d_gpart[(((size_t)hs * kB + b0 + 1) * kH + k1) * 4 + g1] = f1.y;
        d_gpart[(((size_t)hs * kB + b0) * kH + k2) * 4 + g2] = f2.x;
        d_gpart[(((size_t)hs * kB + b0 + 1) * kH + k2) * 4 + g2] = f2.y;
    }
}

// ---- fused phase: B partial + flag-sync + cooperative C2 ----
__device__ void phaseBC(int t, const float* __restrict__ bc, const float* __restrict__ tn,
                        const float* __restrict__ bias, float* __restrict__ out,
                        float* s_f, int* s_i, float* s_s) {
    int u = blockIdx.x;            // < 256
    int b = u >> 3, ch = u & 7;
    int p = t & 1;
    int v0 = ch * 640;
    int tid = threadIdx.x;

    float m = -1e30f; int mi = 0x7fffffff; float se = 0.f;
    int v = v0 + 4 * tid;
    if (tid < 160 && v < kV) {
        float4 s = *(const float4*)&bc[v];
#pragma unroll
        for (int hs = 0; hs < HS; hs++) {
            float4 pp = *(const float4*)&d_part[((size_t)(hs * kB + b)) * kV + v];
            s.x += pp.x; s.y += pp.y; s.z += pp.z; s.w += pp.w;
        }
        se = expf(s.x) + expf(s.y) + expf(s.z) + expf(s.w);
        m = s.x; mi = v;
        if (s.y > m) { m = s.y; mi = v + 1; }
        if (s.z > m) { m = s.z; mi = v + 2; }
        if (s.w > m) { m = s.w; mi = v + 3; }
    }
    s_f[tid] = m; s_i[tid] = mi; s_s[tid] = se;
    __syncthreads();
    for (int w = 128; w; w >>= 1) {
        if (tid < w) {
            float om = s_f[tid + w]; int oi = s_i[tid + w];
            if (om > s_f[tid] || (om == s_f[tid] && oi < s_i[tid])) { s_f[tid] = om; s_i[tid] = oi; }
            s_s[tid] += s_s[tid + w];
        }
        __syncthreads();
    }
    if (tid == 0) {
        d_bmax[u] = s_f[0]; d_bidx[u] = s_i[0]; d_bsum[u] = s_s[0];
        d_bcnt[p ^ 1][b] = 0;
        __threadfence();
        atomicAdd(&d_bcnt[p][b], 1);
        while (ld_cg_i(&d_bcnt[p][b]) < BCH) { __nanosleep(20); }
    }
    __syncthreads();

    float M = -1e30f; int MI = 0; float S = 0.f;
#pragma unroll
    for (int c = 0; c < BCH; c++) {
        float cm = __ldcg(&d_bmax[b * BCH + c]);
        int ci = __ldcg(&d_bidx[b * BCH + c]);
        S += __ldcg(&d_bsum[b * BCH + c]);
        if (cm > M) { M = cm; MI = ci; }
    }
    int upd = (MI != 0);
    int nt = upd ? MI : ld_cg_i(&d_tok[b]);

    if (t < kT - 1 && tid < 80) {      // this block owns k in [ch*80, ch*80+80)
        int k = ch * 80 + tid;
        float hnew;
        if (upd) {
            float4 a = *(const float4*)&d_xwx[((size_t)nt * kH + k) * 4];
            a.x += bias[k]; a.y += bias[kH + k];
            a.z += bias[2 * kH + k]; a.w += bias[3 * kH + k];
#pragma unroll
            for (int hs = 0; hs < HS; hs++) {
                float4 pp = *(const float4*)&d_gpart[(((size_t)hs * kB + b) * kH + k) * 4];
                a.x += pp.x; a.y += pp.y; a.z += pp.z; a.w += pp.w;
            }
            float cold = d_c[b * kH + k];
            float c2v = sigf(a.y) * cold + sigf(a.x) * tanhf(a.z);
            float h2 = sigf(a.w) * tanhf(c2v);
            d_c[b * kH + k] = c2v;
            d_hT[k * kB + b] = h2;
            hnew = h2;
        } else {
            hnew = d_hT[k * kB + b];
        }
        d_jointT[k * kB + b] = tanhf(tn[((size_t)b * kT + (t + 1)) * kH + k] + hnew);
    }

    if (ch == 0 && tid == 0) {
        float val = M - logf(S);
        float sc = d_scores[b] + (upd ? val : 0.f);
        d_scores[b] = sc;
        if (t == kT - 1) out[b] = sc;
        out[kB + (size_t)b * kT + t] = (float)(upd ? MI : 0);
        if (upd) d_tok[b] = MI;
    }
}

// ---- one-time: xWx = embed @ Wx -> [v][k][gate] ----
__device__ void precompute_xwx(const float* __restrict__ embed, const float* __restrict__ Wx,
                               float (*sA)[16]) {
    for (int tp = blockIdx.x; tp < PT; tp += NBLK) {
        int rb = tp / 5, jch = tp % 5;
        int v0 = rb * 16;
        int tid = threadIdx.x;
        int j1 = jch * 512 + 2 * tid;
        int j2 = j1 + 1;
        ull a1[8] = {0, 0, 0, 0, 0, 0, 0, 0}, a2[8] = {0, 0, 0, 0, 0, 0, 0, 0};
        for (int hs = 0; hs < HS; hs++) {
            __syncthreads();
            for (int idx = tid; idx < DEP * 16; idx += NTHR) {
                int hh = idx >> 4, bb = idx & 15;
                int vv = v0 + bb;
                sA[hh][bb] = (vv < kV) ? embed[(size_t)vv * kH + hs * DEP + hh] : 0.f;
            }
            __syncthreads();
            dot40p(a1, a2, sA, Wx + (size_t)(hs * DEP) * kG + j1, kG);
        }
        int g1 = j1 / kH, k1 = j1 - g1 * kH;
        int g2 = j2 / kH, k2 = j2 - g2 * kH;
#pragma unroll
        for (int i = 0; i < 8; i++) {
            float2 f1 = unpack2(a1[i]);
            float2 f2 = unpack2(a2[i]);
            int vv = v0 + 2 * i;
            if (vv < kV) {
                d_xwx[((size_t)vv * kH + k1) * 4 + g1] = f1.x;
                d_xwx[((size_t)vv * kH + k2) * 4 + g2] = f2.x;
            }
            if (vv + 1 < kV) {
                d_xwx[((size_t)(vv + 1) * kH + k1) * 4 + g1] = f1.y;
                d_xwx[((size_t)(vv + 1) * kH + k2) * 4 + g2] = f2.y;
            }
        }
        __syncthreads();
    }
}

__device__ void initC2(const float* __restrict__ tn, const float* __restrict__ bias) {
    int gid = blockIdx.x * NTHR + threadIdx.x;
    if (gid >= kB * kH) return;
    int b = gid / kH, k = gid - b * kH;
    float4 a = *(const float4*)&d_xwx[(size_t)k * 4];
    a.x += bias[k]; a.y += bias[kH + k]; a.z += bias[2 * kH + k]; a.w += bias[3 * kH + k];
    float c1 = sigf(a.x) * tanhf(a.z);
    float h1 = sigf(a.w) * tanhf(c1);
    d_c[gid] = c1;
    d_hT[k * kB + b] = h1;
    d_jointT[k * kB + b] = tanhf(tn[(size_t)b * kT * kH + k] + h1);
    if (k == 0) { d_scores[b] = 0.f; d_tok[b] = 0; d_bcnt[0][b] = 0; d_bcnt[1][b] = 0; }
}

__global__ void __launch_bounds__(NTHR, 4)
transducer_kernel(const float* __restrict__ tn, const float* __restrict__ embed,
                  const float* __restrict__ Wx, const float* __restrict__ Wh,
                  const float* __restrict__ bias, const float* __restrict__ Wc,
                  const float* __restrict__ bc, float* __restrict__ out) {
    __shared__ __align__(16) float sA[DEP][16];
    __shared__ float s_f[NTHR];
    __shared__ int   s_i[NTHR];
    __shared__ float s_s[NTHR];

    precompute_xwx(embed, Wx, sA);
    grid_barrier();
    initC2(tn, bias);
    grid_barrier();

    for (int t = 0; t < kT; ++t) {
        // phase 1: A (joint@Wc) and CH (h@Wh) in parallel, static mapping
        if (blockIdx.x < TILES_A) {
            A_tile(blockIdx.x, sA, Wc);
        } else if (t < kT - 1 && blockIdx.x < TILES_A + TILES_CH) {
            CH_tile(blockIdx.x - TILES_A, sA, Wh);
        }
        grid_barrier();

        // phase 2: fused B -> cooperative C2 (blocks 0..255)
        if (blockIdx.x < kB * BCH) {
            phaseBC(t, bc, tn, bias, out, s_f, s_i, s_s);
        }
        grid_barrier();
    }
}

extern "C" void kernel_launch(void* const* d_in, const int* in_sizes, int n_in,
                              void* d_out, int out_size) {
    const float* tn    = (const float*)d_in[0];
    const float* embed = (const float*)d_in[1];
    const float* Wx    = (const float*)d_in[2];
    const float* Wh    = (const float*)d_in[3];
    const float* bias  = (const float*)d_in[4];
    const float* Wc    = (const float*)d_in[5];
    const float* bc    = (const float*)d_in[6];
    float* out = (float*)d_out;
    (void)in_sizes; (void)n_in; (void)out_size;
    transducer_kernel<<<NBLK, NTHR>>>(tn, embed, Wx, Wh, bias, Wc, bc, out);
}

// round 12
// speedup vs baseline: 1.0820x; 1.0820x over previous
#include <cuda_runtime.h>

// Persistent single-kernel greedy transducer decode. B=32,T=1000,H=640,V=5000.
// Round 11: single batch-group (32 lanes/thread) -> weights stream L2 exactly ONCE
// per step (~100MB vs round-8's ~325MB; LTS cap was the binding resource).
// DEP=64/HS=10, 300 GEMM tiles, 3 blocks/SM, fused B->C2, 2 barriers/step.

typedef unsigned long long ull;

constexpr int kB = 32;
constexpr int kT = 1000;
constexpr int kH = 640;
constexpr int kV = 5000;
constexpr int kG = 2560;

constexpr int NBLK = 444;   // 3 blocks/SM x 148 SMs
constexpr int NTHR = 256;

constexpr int HS = 10, DEP = 64;
constexpr int TILES_A = 200;    // 20 vch(256 cols) x 10 hs
constexpr int TILES_CH = 100;   // 10 jch(256 cols) x 10 hs
constexpr int BCH = 8;          // 8 v-chunks x 32 b = 256 BC-units
constexpr int PT = 1570;        // precompute: 157 rowblocks(32v) x 10 jch

// ---- device globals ----
__device__ __align__(16) float d_xwx[(size_t)kV * kH * 4];
__device__ __align__(16) float d_part[(size_t)HS * kB * kV];       // 6.4MB
__device__ __align__(16) float d_gpart[(size_t)HS * kB * kH * 4];  // 3.3MB
__device__ __align__(16) float d_jointT[kH * kB];
__device__ __align__(16) float d_hT[kH * kB];
__device__ __align__(16) float d_c[kB * kH];
__device__ float d_scores[kB];
__device__ int   d_tok[kB];
__device__ float d_bmax[kB * BCH];
__device__ int   d_bidx[kB * BCH];
__device__ float d_bsum[kB * BCH];
__device__ int   d_bcnt[2][kB];

__device__ __align__(128) unsigned g_count[32];
__device__ __align__(128) unsigned g_gen[32];

__device__ __forceinline__ unsigned ld_cg(const unsigned* p) {
    unsigned v;
    asm volatile("ld.global.cg.u32 %0, [%1];" : "=r"(v) : "l"(p));
    return v;
}
__device__ __forceinline__ int ld_cg_i(const int* p) {
    int v;
    asm volatile("ld.global.cg.s32 %0, [%1];" : "=r"(v) : "l"(p));
    return v;
}

__device__ __forceinline__ void grid_barrier() {
    __syncthreads();
    if (threadIdx.x == 0) {
        __threadfence();
        unsigned my = ld_cg(&g_gen[0]);
        if (atomicAdd(&g_count[0], 1u) == (unsigned)(NBLK - 1)) {
            atomicExch(&g_count[0], 0u);
            __threadfence();
            atomicAdd(&g_gen[0], 1u);
        } else {
            while (ld_cg(&g_gen[0]) == my) { __nanosleep(40); }
        }
        __threadfence();
    }
    __syncthreads();
}

// ---- f32x2 helpers ----
__device__ __forceinline__ ull pack2(float w) {
    ull r; asm("mov.b64 %0, {%1, %1};" : "=l"(r) : "f"(w)); return r;
}
__device__ __forceinline__ void ffma2(ull& a, ull s, ull w) {
    asm("fma.rn.f32x2 %0, %1, %2, %0;" : "+l"(a) : "l"(s), "l"(w));
}
__device__ __forceinline__ float2 unpack2(ull a) {
    float2 f; asm("mov.b64 {%0, %1}, %2;" : "=f"(f.x), "=f"(f.y) : "l"(a)); return f;
}
__device__ __forceinline__ float sigf(float x) { return 1.f / (1.f + expf(-x)); }

// 32-lane x 1-col dot over 64 depth rows. One scalar weight LDG per row (4-deep
// ring), 8 broadcast LDS.128 + 16 FFMA2 per row. acc[i] packs batches 2i,2i+1.
__device__ __forceinline__ void dot64_32(ull acc[16], const float (*sA)[32],
                                         const float* __restrict__ wp, size_t ws) {
    float wb[4];
#pragma unroll
    for (int j = 0; j < 4; j++) wb[j] = wp[j * ws];
    const float* fp = wp + 4 * ws;
#pragma unroll
    for (int g = 0; g < DEP; ++g) {
        float w = wb[g & 3];
        if (g < DEP - 4) { wb[g & 3] = *fp; fp += ws; }
        ull W = pack2(w);
        const double2* sp = reinterpret_cast<const double2*>(sA[g]);
#pragma unroll
        for (int q = 0; q < 4; q++) {
            double2 d = sp[q];
            ffma2(acc[4 * q + 0], __double_as_longlong(d.x), W);
            ffma2(acc[4 * q + 1], __double_as_longlong(d.y), W);
            d = sp[q + 4 < 8 ? q + 4 : q];   // placeholder, replaced below
        }
        // unrolled explicitly to keep staging tight:
        // (the loop above covers q0..q3 lanes 0..15; now lanes 16..31)
        double2 e0 = sp[4], e1 = sp[5], e2 = sp[6], e3 = sp[7];
        ffma2(acc[8],  __double_as_longlong(e0.x), W);
        ffma2(acc[9],  __double_as_longlong(e0.y), W);
        ffma2(acc[10], __double_as_longlong(e1.x), W);
        ffma2(acc[11], __double_as_longlong(e1.y), W);
        ffma2(acc[12], __double_as_longlong(e2.x), W);
        ffma2(acc[13], __double_as_longlong(e2.y), W);
        ffma2(acc[14], __double_as_longlong(e3.x), W);
        ffma2(acc[15], __double_as_longlong(e3.y), W);
    }
}

// Correct clean version (used): lanes 0..15 via q0..q3 without the stray line.
__device__ __forceinline__ void dot64_32b(ull acc[16], const float (*sA)[32],
                                          const float* __restrict__ wp, size_t ws) {
    float wb[4];
#pragma unroll
    for (int j = 0; j < 4; j++) wb[j] = wp[j * ws];
    const float* fp = wp + 4 * ws;
#pragma unroll
    for (int g = 0; g < DEP; ++g) {
        float w = wb[g & 3];
        if (g < DEP - 4) { wb[g & 3] = *fp; fp += ws; }
        ull W = pack2(w);
        const double2* sp = reinterpret_cast<const double2*>(sA[g]);
        double2 d0 = sp[0], d1 = sp[1], d2 = sp[2], d3 = sp[3];
        ffma2(acc[0], __double_as_longlong(d0.x), W);
        ffma2(acc[1], __double_as_longlong(d0.y), W);
        ffma2(acc[2], __double_as_longlong(d1.x), W);
        ffma2(acc[3], __double_as_longlong(d1.y), W);
        ffma2(acc[4], __double_as_longlong(d2.x), W);
        ffma2(acc[5], __double_as_longlong(d2.y), W);
        ffma2(acc[6], __double_as_longlong(d3.x), W);
        ffma2(acc[7], __double_as_longlong(d3.y), W);
        double2 e0 = sp[4], e1 = sp[5], e2 = sp[6], e3 = sp[7];
        ffma2(acc[8],  __double_as_longlong(e0.x), W);
        ffma2(acc[9],  __double_as_longlong(e0.y), W);
        ffma2(acc[10], __double_as_longlong(e1.x), W);
        ffma2(acc[11], __double_as_longlong(e1.y), W);
        ffma2(acc[12], __double_as_longlong(e2.x), W);
        ffma2(acc[13], __double_as_longlong(e2.y), W);
        ffma2(acc[14], __double_as_longlong(e3.x), W);
        ffma2(acc[15], __double_as_longlong(e3.y), W);
    }
}

// Fill [64][32] tile = contiguous 8KB copy from transposed [k][32] source.
__device__ __forceinline__ void fill_T32(float (*dst)[32], const float* __restrict__ srcT,
                                         int hbase) {
    const float4* s = reinterpret_cast<const float4*>(srcT + hbase * kB);
    float4* d = reinterpret_cast<float4*>(&dst[0][0]);
    for (int i = threadIdx.x; i < DEP * 32 / 4; i += NTHR) d[i] = s[i];
}

// ---- A tile: jointT @ Wc -> d_part ----
__device__ void A_tile(int tt, float (*sA)[32], const float* __restrict__ Wc) {
    int vch = tt % 20, hs = tt / 20;
    int hbase = hs * DEP;
    fill_T32(sA, d_jointT, hbase);
    __syncthreads();
    int v = vch * 256 + threadIdx.x;
    if (v < kV) {
        ull acc[16];
#pragma unroll
        for (int i = 0; i < 16; i++) acc[i] = 0ull;
        dot64_32b(acc, sA, Wc + (size_t)hbase * kV + v, kV);
        size_t rb = (size_t)(hs * kB) * kV + v;
#pragma unroll
        for (int i = 0; i < 16; i++) {
            float2 f = unpack2(acc[i]);
            d_part[rb + (size_t)(2 * i) * kV] = f.x;
            d_part[rb + (size_t)(2 * i + 1) * kV] = f.y;
        }
    }
}

// ---- CH tile: hT @ Wh -> d_gpart ----
__device__ void CH_tile(int u, float (*sA)[32], const float* __restrict__ Wh) {
    int jch = u % 10, hs = u / 10;
    int hbase = hs * DEP;
    fill_T32(sA, d_hT, hbase);
    __syncthreads();
    int j = jch * 256 + threadIdx.x;
    ull acc[16];
#pragma unroll
    for (int i = 0; i < 16; i++) acc[i] = 0ull;
    dot64_32b(acc, sA, Wh + (size_t)hbase * kG + j, kG);
    int gate = j / kH, k = j - gate * kH;
#pragma unroll
    for (int i = 0; i < 16; i++) {
        float2 f = unpack2(acc[i]);
        d_gpart[(((size_t)hs * kB + 2 * i) * kH + k) * 4 + gate] = f.x;
        d_gpart[(((size_t)hs * kB + 2 * i + 1) * kH + k) * 4 + gate] = f.y;
    }
}

// ---- fused phase: B partial + flag-sync + cooperative C2 ----
__device__ void phaseBC(int t, const float* __restrict__ bc, const float* __restrict__ tn,
                        const float* __restrict__ bias, float* __restrict__ out,
                        float* s_f, int* s_i, float* s_s) {
    int u = blockIdx.x;            // < 256
    int b = u >> 3, ch = u & 7;
    int p = t & 1;
    int v0 = ch * 640;
    int tid = threadIdx.x;

    float m = -1e30f; int mi = 0x7fffffff; float se = 0.f;
    int v = v0 + 4 * tid;
    if (tid < 160 && v < kV) {
        float4 s = *(const float4*)&bc[v];
#pragma unroll
        for (int hs = 0; hs < HS; hs++) {
            float4 pp = *(const float4*)&d_part[((size_t)(hs * kB + b)) * kV + v];
            s.x += pp.x; s.y += pp.y; s.z += pp.z; s.w += pp.w;
        }
        se = expf(s.x) + expf(s.y) + expf(s.z) + expf(s.w);
        m = s.x; mi = v;
        if (s.y > m) { m = s.y; mi = v + 1; }
        if (s.z > m) { m = s.z; mi = v + 2; }
        if (s.w > m) { m = s.w; mi = v + 3; }
    }
    s_f[tid] = m; s_i[tid] = mi; s_s[tid] = se;
    __syncthreads();
    for (int w = 128; w; w >>= 1) {
        if (tid < w) {
            float om = s_f[tid + w]; int oi = s_i[tid + w];
            if (om > s_f[tid] || (om == s_f[tid] && oi < s_i[tid])) { s_f[tid] = om; s_i[tid] = oi; }
            s_s[tid] += s_s[tid + w];
        }
        __syncthreads();
    }
    if (tid == 0) {
        d_bmax[u] = s_f[0]; d_bidx[u] = s_i[0]; d_bsum[u] = s_s[0];
        d_bcnt[p ^ 1][b] = 0;
        __threadfence();
        atomicAdd(&d_bcnt[p][b], 1);
        while (ld_cg_i(&d_bcnt[p][b]) < BCH) { __nanosleep(20); }
    }
    __syncthreads();

    float M = -1e30f; int MI = 0; float S = 0.f;
#pragma unroll
    for (int c = 0; c < BCH; c++) {
        float cm = __ldcg(&d_bmax[b * BCH + c]);
        int ci = __ldcg(&d_bidx[b * BCH + c]);
        S += __ldcg(&d_bsum[b * BCH + c]);
        if (cm > M) { M = cm; MI = ci; }
    }
    int upd = (MI != 0);
    int nt = upd ? MI : ld_cg_i(&d_tok[b]);

    if (t < kT - 1 && tid < 80) {      // this block owns k in [ch*80, ch*80+80)
        int k = ch * 80 + tid;
        float hnew;
        if (upd) {
            float4 a = *(const float4*)&d_xwx[((size_t)nt * kH + k) * 4];
            a.x += bias[k]; a.y += bias[kH + k];
            a.z += bias[2 * kH + k]; a.w += bias[3 * kH + k];
#pragma unroll
            for (int hs = 0; hs < HS; hs++) {
                float4 pp = *(const float4*)&d_gpart[(((size_t)hs * kB + b) * kH + k) * 4];
                a.x += pp.x; a.y += pp.y; a.z += pp.z; a.w += pp.w;
            }
            float cold = d_c[b * kH + k];
            float c2v = sigf(a.y) * cold + sigf(a.x) * tanhf(a.z);
            float h2 = sigf(a.w) * tanhf(c2v);
            d_c[b * kH + k] = c2v;
            d_hT[k * kB + b] = h2;
            hnew = h2;
        } else {
            hnew = d_hT[k * kB + b];
        }
        d_jointT[k * kB + b] = tanhf(tn[((size_t)b * kT + (t + 1)) * kH + k] + hnew);
    }

    if (ch == 0 && tid == 0) {
        float val = M - logf(S);
        float sc = d_scores[b] + (upd ? val : 0.f);
        d_scores[b] = sc;
        if (t == kT - 1) out[b] = sc;
        out[kB + (size_t)b * kT + t] = (float)(upd ? MI : 0);
        if (upd) d_tok[b] = MI;
    }
}

// ---- one-time: xWx = embed @ Wx -> [v][k][gate] ----
__device__ void precompute_xwx(const float* __restrict__ embed, const float* __restrict__ Wx,
                               float (*sA)[32]) {
    for (int tp = blockIdx.x; tp < PT; tp += NBLK) {
        int rb = tp / 10, jch = tp % 10;
        int v0 = rb * 32;
        int tid = threadIdx.x;
        int j = jch * 256 + tid;
        ull acc[16];
#pragma unroll
        for (int i = 0; i < 16; i++) acc[i] = 0ull;
        for (int hs = 0; hs < HS; hs++) {
            __syncthreads();
            for (int idx = tid; idx < DEP * 32; idx += NTHR) {
                int hh = idx >> 5, bb = idx & 31;
                int vv = v0 + bb;
                sA[hh][bb] = (vv < kV) ? embed[(size_t)vv * kH + hs * DEP + hh] : 0.f;
            }
            __syncthreads();
            dot64_32b(acc, sA, Wx + (size_t)(hs * DEP) * kG + j, kG);
        }
        int gate = j / kH, k = j - gate * kH;
#pragma unroll
        for (int i = 0; i < 16; i++) {
            float2 f = unpack2(acc[i]);
            int vv = v0 + 2 * i;
            if (vv < kV)     d_xwx[((size_t)vv * kH + k) * 4 + gate] = f.x;
            if (vv + 1 < kV) d_xwx[((size_t)(vv + 1) * kH + k) * 4 + gate] = f.y;
        }
        __syncthreads();
    }
}

__device__ void initC2(const float* __restrict__ tn, const float* __restrict__ bias) {
    int gid = blockIdx.x * NTHR + threadIdx.x;
    if (gid >= kB * kH) return;
    int b = gid / kH, k = gid - b * kH;
    float4 a = *(const float4*)&d_xwx[(size_t)k * 4];
    a.x += bias[k]; a.y += bias[kH + k]; a.z += bias[2 * kH + k]; a.w += bias[3 * kH + k];
    float c1 = sigf(a.x) * tanhf(a.z);
    float h1 = sigf(a.w) * tanhf(c1);
    d_c[gid] = c1;
    d_hT[k * kB + b] = h1;
    d_jointT[k * kB + b] = tanhf(tn[(size_t)b * kT * kH + k] + h1);
    if (k == 0) { d_scores[b] = 0.f; d_tok[b] = 0; d_bcnt[0][b] = 0; d_bcnt[1][b] = 0; }
}

__global__ void __launch_bounds__(NTHR, 3)
transducer_kernel(const float* __restrict__ tn, const float* __restrict__ embed,
                  const float* __restrict__ Wx, const float* __restrict__ Wh,
                  const float* __restrict__ bias, const float* __restrict__ Wc,
                  const float* __restrict__ bc, float* __restrict__ out) {
    __shared__ __align__(16) float sA[DEP][32];
    __shared__ float s_f[NTHR];
    __shared__ int   s_i[NTHR];
    __shared__ float s_s[NTHR];

    precompute_xwx(embed, Wx, sA);
    grid_barrier();
    initC2(tn, bias);
    grid_barrier();

    for (int t = 0; t < kT; ++t) {
        // phase 1: A (joint@Wc) and CH (h@Wh), one tile per block, zero redundancy
        if (blockIdx.x < TILES_A) {
            A_tile(blockIdx.x, sA, Wc);
        } else if (t < kT - 1 && blockIdx.x < TILES_A + TILES_CH) {
            CH_tile(blockIdx.x - TILES_A, sA, Wh);
        }
        grid_barrier();

        // phase 2: fused B -> cooperative C2 (blocks 0..255)
        if (blockIdx.x < kB * BCH) {
            phaseBC(t, bc, tn, bias, out, s_f, s_i, s_s);
        }
        grid_barrier();
    }
}

extern "C" void kernel_launch(void* const* d_in, const int* in_sizes, int n_in,
                              void* d_out, int out_size) {
    const float* tn    = (const float*)d_in[0];
    const float* embed = (const float*)d_in[1];
    const float* Wx    = (const float*)d_in[2];
    const float* Wh    = (const float*)d_in[3];
    const float* bias  = (const float*)d_in[4];
    const float* Wc    = (const float*)d_in[5];
    const float* bc    = (const float*)d_in[6];
    float* out = (float*)d_out;
    (void)in_sizes; (void)n_in; (void)out_size;
    transducer_kernel<<<NBLK, NTHR>>>(tn, embed, Wx, Wh, bias, Wc, bc, out);
}

// round 13
// speedup vs baseline: 1.1384x; 1.0522x over previous
#include <cuda_runtime.h>

// Persistent single-kernel greedy transducer decode. B=32,T=1000,H=640,V=5000.
// Round 12: round-8 geometry exactly (DEP=80/HS=8, 480 tiles, 4 blk/SM, fused BC),
// single delta: thread tile B=16 x C=1 -> weight streaming halved (2 bg not 4).

typedef unsigned long long ull;

constexpr int kB = 32;
constexpr int kT = 1000;
constexpr int kH = 640;
constexpr int kV = 5000;
constexpr int kG = 2560;

constexpr int NBLK = 592;   // 4 blocks/SM x 148 SMs
constexpr int NTHR = 256;

constexpr int HS = 8, DEP = 80;
constexpr int TILES_A = 320;    // 20 vch(256 cols) x 8 hs x 2 bg(16b)
constexpr int TILES_CH = 160;   // 10 jch(256 cols) x 8 hs x 2 bg
constexpr int BCH = 8;          // 8 v-chunks x 32 b = 256 BC-units
constexpr int PT = 3130;        // precompute: 313 rowblocks(16v) x 10 jch

// ---- device globals ----
__device__ __align__(16) float d_xwx[(size_t)kV * kH * 4];
__device__ __align__(16) float d_part[(size_t)HS * kB * kV];       // 5.12MB
__device__ __align__(16) float d_gpart[(size_t)HS * kB * kH * 4];  // 2.62MB
__device__ __align__(16) float d_jointT[kH * kB];
__device__ __align__(16) float d_hT[kH * kB];
__device__ __align__(16) float d_c[kB * kH];
__device__ float d_scores[kB];
__device__ int   d_tok[kB];
__device__ float d_bmax[kB * BCH];
__device__ int   d_bidx[kB * BCH];
__device__ float d_bsum[kB * BCH];
__device__ int   d_bcnt[2][kB];

__device__ __align__(128) unsigned g_count[32];
__device__ __align__(128) unsigned g_gen[32];

__device__ __forceinline__ unsigned ld_cg(const unsigned* p) {
    unsigned v;
    asm volatile("ld.global.cg.u32 %0, [%1];" : "=r"(v) : "l"(p));
    return v;
}
__device__ __forceinline__ int ld_cg_i(const int* p) {
    int v;
    asm volatile("ld.global.cg.s32 %0, [%1];" : "=r"(v) : "l"(p));
    return v;
}

__device__ __forceinline__ void grid_barrier() {
    __syncthreads();
    if (threadIdx.x == 0) {
        __threadfence();
        unsigned my = ld_cg(&g_gen[0]);
        if (atomicAdd(&g_count[0], 1u) == (unsigned)(NBLK - 1)) {
            atomicExch(&g_count[0], 0u);
            __threadfence();
            atomicAdd(&g_gen[0], 1u);
        } else {
            while (ld_cg(&g_gen[0]) == my) { __nanosleep(40); }
        }
        __threadfence();
    }
    __syncthreads();
}

// ---- f32x2 helpers ----
__device__ __forceinline__ ull pack2(float w) {
    ull r; asm("mov.b64 %0, {%1, %1};" : "=l"(r) : "f"(w)); return r;
}
__device__ __forceinline__ void ffma2(ull& a, ull s, ull w) {
    asm("fma.rn.f32x2 %0, %1, %2, %0;" : "+l"(a) : "l"(s), "l"(w));
}
__device__ __forceinline__ float2 unpack2(ull a) {
    float2 f; asm("mov.b64 {%0, %1}, %2;" : "=f"(f.x), "=f"(f.y) : "l"(a)); return f;
}
__device__ __forceinline__ float sigf(float x) { return 1.f / (1.f + expf(-x)); }

// B=16 x C=1 dot over 80 depth rows. Per row: 1 scalar weight LDG (8-deep ring),
// 4 broadcast LDS.128, 8 FFMA2. acc[i] packs batches 2i,2i+1 of the group.
__device__ __forceinline__ void dot80_16(ull acc[8], const float (*sA)[16],
                                         const float* __restrict__ wp, size_t ws) {
    float wb[8];
#pragma unroll
    for (int j = 0; j < 8; j++) wb[j] = wp[j * ws];
    const float* fp = wp + 8 * ws;
#pragma unroll
    for (int g = 0; g < DEP; ++g) {
        float w = wb[g & 7];
        if (g < DEP - 8) { wb[g & 7] = *fp; fp += ws; }
        ull W = pack2(w);
        const double2* sp = reinterpret_cast<const double2*>(sA[g]);
        double2 q0 = sp[0], q1 = sp[1], q2 = sp[2], q3 = sp[3];
        ffma2(acc[0], __double_as_longlong(q0.x), W);
        ffma2(acc[1], __double_as_longlong(q0.y), W);
        ffma2(acc[2], __double_as_longlong(q1.x), W);
        ffma2(acc[3], __double_as_longlong(q1.y), W);
        ffma2(acc[4], __double_as_longlong(q2.x), W);
        ffma2(acc[5], __double_as_longlong(q2.y), W);
        ffma2(acc[6], __double_as_longlong(q3.x), W);
        ffma2(acc[7], __double_as_longlong(q3.y), W);
    }
}

// Fill [80][16] tile from transposed [k][32] source (coalesced 64B rows).
__device__ __forceinline__ void fill_T16(float (*dst)[16], const float* __restrict__ srcT,
                                         int bg, int hbase) {
    for (int idx = threadIdx.x; idx < DEP * 16; idx += NTHR) {
        int hh = idx >> 4, bb = idx & 15;
        dst[hh][bb] = srcT[(hbase + hh) * kB + bg * 16 + bb];
    }
}

// ---- A tile: jointT @ Wc -> d_part ----
__device__ void A_tile(int tt, float (*sA)[16], const float* __restrict__ Wc) {
    int hs = tt & 7, vch = (tt >> 3) % 20, bg = tt / 160;
    int hbase = hs * DEP;
    fill_T16(sA, d_jointT, bg, hbase);
    __syncthreads();
    int v = vch * 256 + threadIdx.x;
    if (v < kV) {
        ull acc[8] = {0, 0, 0, 0, 0, 0, 0, 0};
        dot80_16(acc, sA, Wc + (size_t)hbase * kV + v, kV);
        size_t rb = (size_t)(hs * kB + bg * 16) * kV + v;
#pragma unroll
        for (int i = 0; i < 8; i++) {
            float2 f = unpack2(acc[i]);
            d_part[rb + (size_t)(2 * i) * kV] = f.x;
            d_part[rb + (size_t)(2 * i + 1) * kV] = f.y;
        }
    }
}

// ---- CH tile: hT @ Wh -> d_gpart ----
__device__ void CH_tile(int u, float (*sA)[16], const float* __restrict__ Wh) {
    int hs = u & 7, jch = (u >> 3) % 10, bg = u / 80;
    int hbase = hs * DEP;
    fill_T16(sA, d_hT, bg, hbase);
    __syncthreads();
    int j = jch * 256 + threadIdx.x;
    ull acc[8] = {0, 0, 0, 0, 0, 0, 0, 0};
    dot80_16(acc, sA, Wh + (size_t)hbase * kG + j, kG);
    int gate = j / kH, k = j - gate * kH;
#pragma unroll
    for (int i = 0; i < 8; i++) {
        float2 f = unpack2(acc[i]);
        int b0 = bg * 16 + 2 * i;
        d_gpart[(((size_t)hs * kB + b0) * kH + k) * 4 + gate] = f.x;
        d_gpart[(((size_t)hs * kB + b0 + 1) * kH + k) * 4 + gate] = f.y;
    }
}

// ---- fused phase: B partial + flag-sync + cooperative C2 ----
__device__ void phaseBC(int t, const float* __restrict__ bc, const float* __restrict__ tn,
                        const float* __restrict__ bias, float* __restrict__ out,
                        float* s_f, int* s_i, float* s_s) {
    int u = blockIdx.x;            // < 256
    int b = u >> 3, ch = u & 7;
    int p = t & 1;
    int v0 = ch * 640;
    int tid = threadIdx.x;

    float m = -1e30f; int mi = 0x7fffffff; float se = 0.f;
    int v = v0 + 4 * tid;
    if (tid < 160 && v < kV) {
        float4 s = *(const float4*)&bc[v];
#pragma unroll
        for (int hs = 0; hs < HS; hs++) {
            float4 pp = *(const float4*)&d_part[((size_t)(hs * kB + b)) * kV + v];
            s.x += pp.x; s.y += pp.y; s.z += pp.z; s.w += pp.w;
        }
        se = expf(s.x) + expf(s.y) + expf(s.z) + expf(s.w);
        m = s.x; mi = v;
        if (s.y > m) { m = s.y; mi = v + 1; }
        if (s.z > m) { m = s.z; mi = v + 2; }
        if (s.w > m) { m = s.w; mi = v + 3; }
    }
    s_f[tid] = m; s_i[tid] = mi; s_s[tid] = se;
    __syncthreads();
    for (int w = 128; w; w >>= 1) {
        if (tid < w) {
            float om = s_f[tid + w]; int oi = s_i[tid + w];
            if (om > s_f[tid] || (om == s_f[tid] && oi < s_i[tid])) { s_f[tid] = om; s_i[tid] = oi; }
            s_s[tid] += s_s[tid + w];
        }
        __syncthreads();
    }
    if (tid == 0) {
        d_bmax[u] = s_f[0]; d_bidx[u] = s_i[0]; d_bsum[u] = s_s[0];
        d_bcnt[p ^ 1][b] = 0;
        __threadfence();
        atomicAdd(&d_bcnt[p][b], 1);
        while (ld_cg_i(&d_bcnt[p][b]) < BCH) { __nanosleep(20); }
    }
    __syncthreads();

    float M = -1e30f; int MI = 0; float S = 0.f;
#pragma unroll
    for (int c = 0; c < BCH; c++) {
        float cm = __ldcg(&d_bmax[b * BCH + c]);
        int ci = __ldcg(&d_bidx[b * BCH + c]);
        S += __ldcg(&d_bsum[b * BCH + c]);
        if (cm > M) { M = cm; MI = ci; }
    }
    int upd = (MI != 0);
    int nt = upd ? MI : ld_cg_i(&d_tok[b]);

    if (t < kT - 1 && tid < 80) {      // this block owns k in [ch*80, ch*80+80)
        int k = ch * 80 + tid;
        float hnew;
        if (upd) {
            float4 a = *(const float4*)&d_xwx[((size_t)nt * kH + k) * 4];
            a.x += bias[k]; a.y += bias[kH + k];
            a.z += bias[2 * kH + k]; a.w += bias[3 * kH + k];
#pragma unroll
            for (int hs = 0; hs < HS; hs++) {
                float4 pp = *(const float4*)&d_gpart[(((size_t)hs * kB + b) * kH + k) * 4];
                a.x += pp.x; a.y += pp.y; a.z += pp.z; a.w += pp.w;
            }
            float cold = d_c[b * kH + k];
            float c2v = sigf(a.y) * cold + sigf(a.x) * tanhf(a.z);
            float h2 = sigf(a.w) * tanhf(c2v);
            d_c[b * kH + k] = c2v;
            d_hT[k * kB + b] = h2;
            hnew = h2;
        } else {
            hnew = d_hT[k * kB + b];
        }
        d_jointT[k * kB + b] = tanhf(tn[((size_t)b * kT + (t + 1)) * kH + k] + hnew);
    }

    if (ch == 0 && tid == 0) {
        float val = M - logf(S);
        float sc = d_scores[b] + (upd ? val : 0.f);
        d_scores[b] = sc;
        if (t == kT - 1) out[b] = sc;
        out[kB + (size_t)b * kT + t] = (float)(upd ? MI : 0);
        if (upd) d_tok[b] = MI;
    }
}

// ---- one-time: xWx = embed @ Wx -> [v][k][gate] ----
__device__ void precompute_xwx(const float* __restrict__ embed, const float* __restrict__ Wx,
                               float (*sA)[16]) {
    for (int tp = blockIdx.x; tp < PT; tp += NBLK) {
        int rb = tp / 10, jch = tp % 10;
        int v0 = rb * 16;
        int tid = threadIdx.x;
        int j = jch * 256 + tid;
        ull acc[8] = {0, 0, 0, 0, 0, 0, 0, 0};
        for (int hs = 0; hs < HS; hs++) {
            __syncthreads();
            for (int idx = tid; idx < DEP * 16; idx += NTHR) {
                int hh = idx >> 4, bb = idx & 15;
                int vv = v0 + bb;
                sA[hh][bb] = (vv < kV) ? embed[(size_t)vv * kH + hs * DEP + hh] : 0.f;
            }
            __syncthreads();
            dot80_16(acc, sA, Wx + (size_t)(hs * DEP) * kG + j, kG);
        }
        int gate = j / kH, k = j - gate * kH;
#pragma unroll
        for (int i = 0; i < 8; i++) {
            float2 f = unpack2(acc[i]);
            int vv = v0 + 2 * i;
            if (vv < kV)     d_xwx[((size_t)vv * kH + k) * 4 + gate] = f.x;
            if (vv + 1 < kV) d_xwx[((size_t)(vv + 1) * kH + k) * 4 + gate] = f.y;
        }
        __syncthreads();
    }
}

__device__ void initC2(const float* __restrict__ tn, const float* __restrict__ bias) {
    int gid = blockIdx.x * NTHR + threadIdx.x;
    if (gid >= kB * kH) return;
    int b = gid / kH, k = gid - b * kH;
    float4 a = *(const float4*)&d_xwx[(size_t)k * 4];
    a.x += bias[k]; a.y += bias[kH + k]; a.z += bias[2 * kH + k]; a.w += bias[3 * kH + k];
    float c1 = sigf(a.x) * tanhf(a.z);
    float h1 = sigf(a.w) * tanhf(c1);
    d_c[gid] = c1;
    d_hT[k * kB + b] = h1;
    d_jointT[k * kB + b] = tanhf(tn[(size_t)b * kT * kH + k] + h1);
    if (k == 0) { d_scores[b] = 0.f; d_tok[b] = 0; d_bcnt[0][b] = 0; d_bcnt[1][b] = 0; }
}

__global__ void __launch_bounds__(NTHR, 4)
transducer_kernel(const float* __restrict__ tn, const float* __restrict__ embed,
                  const float* __restrict__ Wx, const float* __restrict__ Wh,
                  const float* __restrict__ bias, const float* __restrict__ Wc,
                  const float* __restrict__ bc, float* __restrict__ out) {
    __shared__ __align__(16) float sA[DEP][16];
    __shared__ float s_f[NTHR];
    __shared__ int   s_i[NTHR];
    __shared__ float s_s[NTHR];

    precompute_xwx(embed, Wx, sA);
    grid_barrier();
    initC2(tn, bias);
    grid_barrier();

    for (int t = 0; t < kT; ++t) {
        // phase 1: A (joint@Wc) and CH (h@Wh) in parallel, static 480-tile pool
        if (blockIdx.x < TILES_A) {
            A_tile(blockIdx.x, sA, Wc);
        } else if (t < kT - 1 && blockIdx.x < TILES_A + TILES_CH) {
            CH_tile(blockIdx.x - TILES_A, sA, Wh);
        }
        grid_barrier();

        // phase 2: fused B -> cooperative C2 (blocks 0..255)
        if (blockIdx.x < kB * BCH) {
            phaseBC(t, bc, tn, bias, out, s_f, s_i, s_s);
        }
        grid_barrier();
    }
}

extern "C" void kernel_launch(void* const* d_in, const int* in_sizes, int n_in,
                              void* d_out, int out_size) {
    const float* tn    = (const float*)d_in[0];
    const float* embed = (const float*)d_in[1];
    const float* Wx    = (const float*)d_in[2];
    const float* Wh    = (const float*)d_in[3];
    const float* bias  = (const float*)d_in[4];
    const float* Wc    = (const float*)d_in[5];
    const float* bc    = (const float*)d_in[6];
    float* out = (float*)d_out;
    (void)in_sizes; (void)n_in; (void)out_size;
    transducer_kernel<<<NBLK, NTHR>>>(tn, embed, Wx, Wh, bias, Wc, bc, out);
}